// round 12
// baseline (speedup 1.0000x reference)
#include <cuda_runtime.h>

#define NT 8192          // true rows
#define NP 8192          // pred cols
#define CAPR 31          // max candidates kept per row (fits 5-bit cnt field)
#define MAXC 12288       // max total compacted candidates (expected ~8.8K)
#define NCELL 8000       // 20x20x20 unit cells
#define CELLCAP 16       // slots per cell (lambda ~0.51 occupied/cell)

// Scratch (device globals — allocation-free; zero-initialized at module load,
// and greedy_match re-zeroes g_cellcnt at the end of every run).
__device__ int g_cellcnt[NCELL];
__device__ float4 g_pts[NCELL * CELLCAP];       // xyz + pred index as int bits
__device__ unsigned long long g_pack;           // hi32 = ngroups, lo32 = ncand total
__device__ unsigned g_meta[NT];                 // row<<19 | cnt<<14 | offset
__device__ unsigned long long g_ccand[MAXC];    // key = (f32bits(d) << 13) | j
__device__ int g_occ;                           // count of occupied true points

__device__ __forceinline__ void pdl_wait() {
    asm volatile("griddepcontrol.wait;" ::: "memory");
}

__device__ __forceinline__ int cell_of(float x, float y, float z) {
    const int cx = min(19, (int)x);
    const int cy = min(19, (int)y);
    const int cz = min(19, (int)z);
    return (cx * 20 + cy) * 20 + cz;
}

// ---------------------------------------------------------------------------
// Phase 1a: bin occupied preds into fixed-capacity cells; reset run counters.
// ---------------------------------------------------------------------------
__global__ __launch_bounds__(256) void bin_points(const float4* __restrict__ pred) {
    const int i = blockIdx.x * 256 + threadIdx.x;
    if (i == 0) { g_pack = 0ULL; g_occ = 0; }
    const float4 p = pred[i];
    if (p.w >= 0.5f) {
        const int c = cell_of(p.x, p.y, p.z);
        const int idx = atomicAdd(&g_cellcnt[c], 1);
        if (idx < CELLCAP)
            g_pts[c * CELLCAP + idx] = make_float4(p.x, p.y, p.z, __int_as_float(i));
    }
}

// ---------------------------------------------------------------------------
// Phase 1b: candidate generation, WARP per true row; lane L<27 owns one of the
// 3x3x3 neighbor cells. PDL secondary: tru[] load + cell math pre-wait.
// ---------------------------------------------------------------------------
#define WPB 8   // warps per block
__global__ __launch_bounds__(256) void build_cand(const float4* __restrict__ tru) {
    __shared__ unsigned long long stage[WPB][32];
    __shared__ int s_cnt[WPB];
    __shared__ int s_occ;
    const int wip  = threadIdx.x >> 5;
    const int lane = threadIdx.x & 31;
    const int row  = blockIdx.x * WPB + wip;

    if (threadIdx.x == 0) s_occ = 0;
    if (lane == 0) s_cnt[wip] = 0;

    // input-independent prologue: load true point, compute neighbor cell
    const float4 t = tru[row];
    const bool occ = (t.w >= 0.5f);
    int c = -1;
    if (occ && lane < 27) {
        const int cx = min(19, (int)t.x);
        const int cy = min(19, (int)t.y);
        const int cz = min(19, (int)t.z);
        const int X = cx + lane / 9 - 1;
        const int Y = cy + (lane / 3) % 3 - 1;
        const int Z = cz + lane % 3 - 1;
        if (X >= 0 && X < 20 && Y >= 0 && Y < 20 && Z >= 0 && Z < 20)
            c = (X * 20 + Y) * 20 + Z;
    }
    __syncthreads();

    pdl_wait();   // bin_points output (g_cellcnt, g_pts, g_pack=0) now visible

    if (c >= 0) {
        const int cnt = min(g_cellcnt[c], CELLCAP);
        for (int e = 0; e < cnt; e++) {
            const float4 p = g_pts[c * CELLCAP + e];
            const float dx = t.x - p.x, dy = t.y - p.y, dz = t.z - p.z;
            float d2 = dx * dx;
            d2 = fmaf(dy, dy, d2);
            d2 = fmaf(dz, dz, d2);
            if (d2 <= 1.0000002f) {
                const float d = __fsqrt_rn(d2);
                if (d <= 1.0f) {
                    const int idx = atomicAdd(&s_cnt[wip], 1);
                    if (idx < CAPR)
                        stage[wip][idx] =
                            (((unsigned long long)__float_as_uint(d)) << 13) |
                            (unsigned)__float_as_int(p.w);
                }
            }
        }
    }
    __syncwarp();

    const int cnt = min(s_cnt[wip], CAPR);
    int base = 0;
    if (lane == 0 && cnt > 0) {
        const unsigned long long old =
            atomicAdd(&g_pack, (1ULL << 32) | (unsigned long long)(unsigned)cnt);
        const unsigned gidx = (unsigned)(old >> 32);
        base = (int)(old & 0xFFFFFFFFu);
        const int wcnt = (base + cnt <= MAXC) ? cnt : 0;   // overflow guard (p~0)
        g_meta[gidx] = ((unsigned)row << 19) | ((unsigned)wcnt << 14) |
                       (unsigned)(base & 16383);
    }
    base = __shfl_sync(0xFFFFFFFFu, base, 0);
    if (lane < cnt && base + lane < MAXC) g_ccand[base + lane] = stage[wip][lane];

    // ONE count per occupied row (warp-per-row: lane 0 only!)
    if (lane == 0 && occ) atomicAdd(&s_occ, 1);
    __syncthreads();
    if (threadIdx.x == 0 && s_occ) atomicAdd(&g_occ, s_occ);
}

// ---------------------------------------------------------------------------
// Phase 2: PDL secondary. Round-based greedy with epoch-tagged colmin.
// NEW: pass B retries unconfirmed rows up to 4x within the round — colmin is
// static after pass A, so the confirm predicate (colmin[j]==epoch|row proves
// no smaller round-start-active row holds j) stays valid for ANY candidate of
// the row all round; mid-round claims only shrink the candidate set. Conflict
// chains (blocker claims the contested column, loser moves to its next
// candidate) now resolve within one round instead of one round per link.
//
// Dynamic smem layout (bytes): unchanged from round 8.
// ---------------------------------------------------------------------------
#define SMEM_BYTES 214432

__global__ __launch_bounds__(1024, 1) void greedy_match(const float4* __restrict__ pred,
                                                        const float4* __restrict__ tru,
                                                        float* __restrict__ out) {
    extern __shared__ unsigned char sm[];
    unsigned long long* s_cand   = (unsigned long long*)sm;
    unsigned*           s_meta   = (unsigned*)(sm + 98304);
    unsigned*           s_colmin = (unsigned*)(sm + 131072);
    unsigned*           s_claim  = (unsigned*)(sm + 163840);
    int*                s_na     = (int*)(sm + 164864);
    float*              s_rd     = (float*)(sm + 164872);
    float*              s_rp     = (float*)(sm + 165000);
    int*                s_rn     = (int*)(sm + 165128);
    unsigned short*     s_listA  = (unsigned short*)(sm + 165256);
    unsigned short*     s_listB  = (unsigned short*)(sm + 181640);
    unsigned short*     s_res    = (unsigned short*)(sm + 198024);

    const int tid  = threadIdx.x;
    const int lane = tid & 31;
    const int wid  = tid >> 5;

    // --- input-independent prologue (overlaps with build_cand via PDL) ---
    if (tid < 256) s_claim[tid] = 0u;
    for (int i = tid; i < NP; i += 1024) s_colmin[i] = 0xFFFFFFFFu;

    pdl_wait();   // build_cand output (g_pack, g_meta, g_ccand, g_occ) visible

    const unsigned long long pack = g_pack;
    const int ngrp = (int)(pack >> 32);
    const int ctot = min((int)(pack & 0xFFFFFFFFu), MAXC);

    // --- bulk coalesced load of compacted state ---
    for (int i = tid; i < ctot; i += 1024) s_cand[i] = g_ccand[i];
    for (int g = tid; g < ngrp; g += 1024) {
        s_meta[g] = g_meta[g];
        s_listA[g] = (unsigned short)g;
    }
    __syncthreads();

    unsigned short* cur = s_listA;
    unsigned short* nxt = s_listB;
    int n = ngrp;
    int par = 0;
    unsigned round = 0;

    // --- block-wide rounds while the active list is large ---
    while (n > 32) {
        const unsigned epoch = (0x3FFFFu - round) << 13;   // strictly decreasing

        // pass A: each active row registers (epoch|row) on ALL its candidates.
        for (int i = tid; i < n; i += 1024) {
            const unsigned m = s_meta[cur[i]];
            const unsigned val = epoch | (m >> 19);
            const int off = (int)(m & 16383u);
            const int end = off + (int)((m >> 14) & 31u);
            for (int e = off; e < end; e++)
                atomicMin(&s_colmin[(unsigned)s_cand[e] & 8191u], val);
        }
        if (tid == 0) s_na[par] = 0;
        __syncthreads();

        // pass B with intra-round retries (chain resolution).
        int pend[8];                       // ceil(8192/1024) = 8 max rows/thread
        int npend = 0;
        for (int i = tid; i < n; i += 1024) pend[npend++] = cur[i];

        for (int it = 0; it < 4 && npend > 0; it++) {
            int w = 0;
            for (int q = 0; q < npend; q++) {
                const int g = pend[q];
                const unsigned m = s_meta[g];
                const unsigned val = epoch | (m >> 19);
                const int off = (int)(m & 16383u);
                const int end = off + (int)((m >> 14) & 31u);
                unsigned long long best = ~0ULL;
                int bestE = -1;
                for (int e = off; e < end; e++) {
                    const unsigned long long cd = s_cand[e];
                    const unsigned j = (unsigned)cd & 8191u;
                    if (!((s_claim[j >> 5] >> (j & 31u)) & 1u) && cd < best) {
                        best = cd;
                        bestE = e;
                    }
                }
                if (best == ~0ULL) {
                    s_res[g] = 0xFFFFu;             // unmatched
                } else {
                    const unsigned j = (unsigned)best & 8191u;
                    if (s_colmin[j] == val) {
                        atomicOr(&s_claim[j >> 5], 1u << (j & 31u));
                        s_res[g] = (unsigned short)bestE;
                    } else {
                        pend[w++] = g;              // retry / carry to next round
                    }
                }
            }
            npend = w;
        }
        if (npend > 0) {
            const int pos = atomicAdd(&s_na[par], npend);
            for (int q = 0; q < npend; q++) nxt[pos + q] = (unsigned short)pend[q];
        }
        __syncthreads();

        n = s_na[par];
        par ^= 1;
        round++;
        unsigned short* tmp = cur; cur = nxt; nxt = tmp;
    }

    // --- tail rounds: warp 0 only, no block barriers ---
    if (wid == 0) {
        while (n > 0) {
            const unsigned epoch = (0x3FFFFu - round) << 13;

            if (lane < n) {
                const unsigned m = s_meta[cur[lane]];
                const unsigned val = epoch | (m >> 19);
                const int off = (int)(m & 16383u);
                const int end = off + (int)((m >> 14) & 31u);
                for (int e = off; e < end; e++)
                    atomicMin(&s_colmin[(unsigned)s_cand[e] & 8191u], val);
            }
            __syncwarp();

            int survive = 0;
            int g = -1;
            if (lane < n) {
                g = cur[lane];
                const unsigned m = s_meta[g];
                const unsigned val = epoch | (m >> 19);
                const int off = (int)(m & 16383u);
                const int end = off + (int)((m >> 14) & 31u);
                // intra-round retries here too (colmin static, claims monotone)
                for (int it = 0; it < 4; it++) {
                    unsigned long long best = ~0ULL;
                    int bestE = -1;
                    for (int e = off; e < end; e++) {
                        const unsigned long long cd = s_cand[e];
                        const unsigned j = (unsigned)cd & 8191u;
                        if (!((s_claim[j >> 5] >> (j & 31u)) & 1u) && cd < best) {
                            best = cd;
                            bestE = e;
                        }
                    }
                    if (best == ~0ULL) {
                        s_res[g] = 0xFFFFu;
                        survive = 0;
                        break;
                    }
                    const unsigned j = (unsigned)best & 8191u;
                    if (s_colmin[j] == val) {
                        atomicOr(&s_claim[j >> 5], 1u << (j & 31u));
                        s_res[g] = (unsigned short)bestE;
                        survive = 0;
                        break;
                    }
                    survive = 1;
                }
            }
            __syncwarp();
            const unsigned sb = __ballot_sync(0xFFFFFFFFu, survive);
            if (survive) {
                const int pos = __popc(sb & ((1u << lane) - 1u));
                nxt[pos] = (unsigned short)g;
            }
            __syncwarp();
            n = __popc(sb);
            round++;
            unsigned short* tmp = cur; cur = nxt; nxt = tmp;
        }
    }
    __syncthreads();

    // --- fixed-order accumulation ---
    const float* truf  = (const float*)tru;
    const float* predf = (const float*)pred;
    float sd = 0.0f, sp = 0.0f;
    int nm = 0;
    for (int g = tid; g < ngrp; g += 1024) {
        const unsigned short r = s_res[g];
        if (r == 0xFFFFu) continue;
        const unsigned long long best = s_cand[r];
        const unsigned row = s_meta[g] >> 19;
        const unsigned j = (unsigned)best & 8191u;
        sd += __uint_as_float((unsigned)(best >> 13));
        nm++;
        const float dp = truf[4 * row + 3] - predf[4 * j + 3];
        sp = fmaf(dp, dp, sp);
    }
#pragma unroll
    for (int o = 16; o > 0; o >>= 1) {
        sd += __shfl_down_sync(0xFFFFFFFFu, sd, o);
        sp += __shfl_down_sync(0xFFFFFFFFu, sp, o);
        nm += __shfl_down_sync(0xFFFFFFFFu, nm, o);
    }
    if (lane == 0) { s_rd[wid] = sd; s_rp[wid] = sp; s_rn[wid] = nm; }

    // re-zero the cell counters for the next replay (graph-deterministic)
    for (int i = tid; i < NCELL; i += 1024) g_cellcnt[i] = 0;

    __syncthreads();
    if (tid == 0) {
        float tsd = 0.0f, tsp = 0.0f;
        int tnm = 0;
        for (int w = 0; w < 32; w++) { tsd += s_rd[w]; tsp += s_rp[w]; tnm += s_rn[w]; }
        const float fnm = (float)tnm;
        const float unm = (float)g_occ - fnm;
        const float mean_dist = tsd / fnm;
        const float prob_mse  = tsp / fnm;
        out[0] = (mean_dist + 10.0f * unm) + (prob_mse + unm);
    }
}

// ---------------------------------------------------------------------------
extern "C" void kernel_launch(void* const* d_in, const int* in_sizes, int n_in,
                              void* d_out, int out_size) {
    const float4* pred = (const float4*)d_in[0];
    const float4* tru  = (const float4*)d_in[1];
    float* out = (float*)d_out;

    bin_points<<<32, 256>>>(pred);

    // build_cand: PDL secondary of bin_points
    {
        cudaLaunchConfig_t cfg = {};
        cfg.gridDim = dim3(1024);
        cfg.blockDim = dim3(256);
        cudaLaunchAttribute attr[1];
        attr[0].id = cudaLaunchAttributeProgrammaticStreamSerialization;
        attr[0].val.programmaticStreamSerializationAllowed = 1;
        cfg.attrs = attr;
        cfg.numAttrs = 1;
        cudaLaunchKernelEx(&cfg, build_cand, tru);
    }

    // greedy_match: PDL secondary of build_cand
    {
        cudaFuncSetAttribute(greedy_match, cudaFuncAttributeMaxDynamicSharedMemorySize,
                             SMEM_BYTES);
        cudaLaunchConfig_t cfg = {};
        cfg.gridDim = dim3(1);
        cfg.blockDim = dim3(1024);
        cfg.dynamicSmemBytes = SMEM_BYTES;
        cudaLaunchAttribute attr[1];
        attr[0].id = cudaLaunchAttributeProgrammaticStreamSerialization;
        attr[0].val.programmaticStreamSerializationAllowed = 1;
        cfg.attrs = attr;
        cfg.numAttrs = 1;
        cudaLaunchKernelEx(&cfg, greedy_match, pred, tru, out);
    }
}

// round 13
// speedup vs baseline: 1.4501x; 1.4501x over previous
#include <cuda_runtime.h>

#define NT 8192          // true rows
#define NP 8192          // pred cols
#define CAPR 31          // max candidates kept per row (fits 5-bit cnt field)
#define MAXC 12288       // max total compacted candidates (expected ~8.8K)
#define NCELL 8000       // 20x20x20 unit cells
#define CELLCAP 16       // slots per cell (lambda ~0.51 occupied/cell)

// Scratch (device globals — allocation-free; zero-initialized at module load,
// and greedy_match re-zeroes g_cellcnt at the end of every run).
__device__ int g_cellcnt[NCELL];
__device__ float4 g_pts[NCELL * CELLCAP];       // xyz + pred index as int bits
__device__ unsigned long long g_pack;           // hi32 = ngroups, lo32 = ncand total
__device__ unsigned g_meta[NT];                 // row<<19 | cnt<<14 | offset
__device__ unsigned long long g_ccand[MAXC];    // key = (f32bits(d) << 13) | j
__device__ int g_occ;                           // count of occupied true points

__device__ __forceinline__ void pdl_wait() {
    asm volatile("griddepcontrol.wait;" ::: "memory");
}

__device__ __forceinline__ int cell_of(float x, float y, float z) {
    const int cx = min(19, (int)x);
    const int cy = min(19, (int)y);
    const int cz = min(19, (int)z);
    return (cx * 20 + cy) * 20 + cz;
}

// ---------------------------------------------------------------------------
// Phase 1a: bin occupied preds into fixed-capacity cells; reset run counters.
// ---------------------------------------------------------------------------
__global__ __launch_bounds__(256) void bin_points(const float4* __restrict__ pred) {
    const int i = blockIdx.x * 256 + threadIdx.x;
    if (i == 0) { g_pack = 0ULL; g_occ = 0; }
    const float4 p = pred[i];
    if (p.w >= 0.5f) {
        const int c = cell_of(p.x, p.y, p.z);
        const int idx = atomicAdd(&g_cellcnt[c], 1);
        if (idx < CELLCAP)
            g_pts[c * CELLCAP + idx] = make_float4(p.x, p.y, p.z, __int_as_float(i));
    }
}

// ---------------------------------------------------------------------------
// Phase 1b: candidate generation, WARP per true row; lane L<27 owns one of the
// 3x3x3 neighbor cells. PDL secondary: tru[] load + cell math pre-wait.
// ---------------------------------------------------------------------------
#define WPB 8   // warps per block
__global__ __launch_bounds__(256) void build_cand(const float4* __restrict__ tru) {
    __shared__ unsigned long long stage[WPB][32];
    __shared__ int s_cnt[WPB];
    __shared__ int s_occ;
    const int wip  = threadIdx.x >> 5;
    const int lane = threadIdx.x & 31;
    const int row  = blockIdx.x * WPB + wip;

    if (threadIdx.x == 0) s_occ = 0;
    if (lane == 0) s_cnt[wip] = 0;

    // input-independent prologue: load true point, compute neighbor cell
    const float4 t = tru[row];
    const bool occ = (t.w >= 0.5f);
    int c = -1;
    if (occ && lane < 27) {
        const int cx = min(19, (int)t.x);
        const int cy = min(19, (int)t.y);
        const int cz = min(19, (int)t.z);
        const int X = cx + lane / 9 - 1;
        const int Y = cy + (lane / 3) % 3 - 1;
        const int Z = cz + lane % 3 - 1;
        if (X >= 0 && X < 20 && Y >= 0 && Y < 20 && Z >= 0 && Z < 20)
            c = (X * 20 + Y) * 20 + Z;
    }
    __syncthreads();

    pdl_wait();   // bin_points output (g_cellcnt, g_pts, g_pack=0) now visible

    if (c >= 0) {
        const int cnt = min(g_cellcnt[c], CELLCAP);
        for (int e = 0; e < cnt; e++) {
            const float4 p = g_pts[c * CELLCAP + e];
            const float dx = t.x - p.x, dy = t.y - p.y, dz = t.z - p.z;
            float d2 = dx * dx;
            d2 = fmaf(dy, dy, d2);
            d2 = fmaf(dz, dz, d2);
            if (d2 <= 1.0000002f) {
                const float d = __fsqrt_rn(d2);
                if (d <= 1.0f) {
                    const int idx = atomicAdd(&s_cnt[wip], 1);
                    if (idx < CAPR)
                        stage[wip][idx] =
                            (((unsigned long long)__float_as_uint(d)) << 13) |
                            (unsigned)__float_as_int(p.w);
                }
            }
        }
    }
    __syncwarp();

    const int cnt = min(s_cnt[wip], CAPR);
    int base = 0;
    if (lane == 0 && cnt > 0) {
        const unsigned long long old =
            atomicAdd(&g_pack, (1ULL << 32) | (unsigned long long)(unsigned)cnt);
        const unsigned gidx = (unsigned)(old >> 32);
        base = (int)(old & 0xFFFFFFFFu);
        const int wcnt = (base + cnt <= MAXC) ? cnt : 0;   // overflow guard (p~0)
        g_meta[gidx] = ((unsigned)row << 19) | ((unsigned)wcnt << 14) |
                       (unsigned)(base & 16383);
    }
    base = __shfl_sync(0xFFFFFFFFu, base, 0);
    if (lane < cnt && base + lane < MAXC) g_ccand[base + lane] = stage[wip][lane];

    // ONE count per occupied row (warp-per-row: lane 0 only!)
    if (lane == 0 && occ) atomicAdd(&s_occ, 1);
    __syncthreads();
    if (threadIdx.x == 0 && s_occ) atomicAdd(&g_occ, s_occ);
}

// ---------------------------------------------------------------------------
// Phase 2: PDL secondary. Round-based greedy, epoch-tagged colmin (no clear
// pass), identity active list in round 0 (all groups active => cur[i]==i, no
// list init/load needed), ping-pong u16 lists from round 1, warp-0 tail.
// Confirm predicate: colmin[j]==(epoch|row) proves no smaller active row
// holds j this round => safe to claim (matches the sequential greedy).
//
// Dynamic smem layout (bytes): unchanged from round 8.
// ---------------------------------------------------------------------------
#define SMEM_BYTES 214432

__global__ __launch_bounds__(1024, 1) void greedy_match(const float4* __restrict__ pred,
                                                        const float4* __restrict__ tru,
                                                        float* __restrict__ out) {
    extern __shared__ unsigned char sm[];
    unsigned long long* s_cand   = (unsigned long long*)sm;
    unsigned*           s_meta   = (unsigned*)(sm + 98304);
    unsigned*           s_colmin = (unsigned*)(sm + 131072);
    unsigned*           s_claim  = (unsigned*)(sm + 163840);
    int*                s_na     = (int*)(sm + 164864);
    float*              s_rd     = (float*)(sm + 164872);
    float*              s_rp     = (float*)(sm + 165000);
    int*                s_rn     = (int*)(sm + 165128);
    unsigned short*     s_listA  = (unsigned short*)(sm + 165256);
    unsigned short*     s_listB  = (unsigned short*)(sm + 181640);
    unsigned short*     s_res    = (unsigned short*)(sm + 198024);

    const int tid  = threadIdx.x;
    const int lane = tid & 31;
    const int wid  = tid >> 5;

    // --- input-independent prologue (overlaps with build_cand via PDL) ---
    if (tid < 256) s_claim[tid] = 0u;
    for (int i = tid; i < NP; i += 1024) s_colmin[i] = 0xFFFFFFFFu;

    pdl_wait();   // build_cand output (g_pack, g_meta, g_ccand, g_occ) visible

    const unsigned long long pack = g_pack;
    const int ngrp = (int)(pack >> 32);
    const int ctot = min((int)(pack & 0xFFFFFFFFu), MAXC);

    // --- bulk coalesced load of compacted state ---
    for (int i = tid; i < ctot; i += 1024) s_cand[i] = g_ccand[i];
    for (int g = tid; g < ngrp; g += 1024) s_meta[g] = g_meta[g];
    __syncthreads();

    // ---------------- round 0: identity active list ----------------
    {
        const unsigned epoch = 0x3FFFFu << 13;

        for (int g = tid; g < ngrp; g += 1024) {
            const unsigned m = s_meta[g];
            const unsigned val = epoch | (m >> 19);
            const int off = (int)(m & 16383u);
            const int end = off + (int)((m >> 14) & 31u);
            for (int e = off; e < end; e++)
                atomicMin(&s_colmin[(unsigned)s_cand[e] & 8191u], val);
        }
        if (tid == 0) s_na[0] = 0;
        __syncthreads();

        for (int g = tid; g < ngrp; g += 1024) {
            const unsigned m = s_meta[g];
            const unsigned val = epoch | (m >> 19);
            const int off = (int)(m & 16383u);
            const int end = off + (int)((m >> 14) & 31u);
            unsigned long long best = ~0ULL;
            int bestE = -1;
            for (int e = off; e < end; e++) {
                const unsigned long long cd = s_cand[e];
                const unsigned j = (unsigned)cd & 8191u;
                if (!((s_claim[j >> 5] >> (j & 31u)) & 1u) && cd < best) {
                    best = cd;
                    bestE = e;
                }
            }
            if (best == ~0ULL) {
                s_res[g] = 0xFFFFu;                 // unmatched
            } else {
                const unsigned j = (unsigned)best & 8191u;
                if (s_colmin[j] == val) {
                    atomicOr(&s_claim[j >> 5], 1u << (j & 31u));
                    s_res[g] = (unsigned short)bestE;
                } else {
                    s_listA[atomicAdd(&s_na[0], 1)] = (unsigned short)g;
                }
            }
        }
        __syncthreads();
    }

    unsigned short* cur = s_listA;
    unsigned short* nxt = s_listB;
    int n = s_na[0];
    int par = 1;
    unsigned round = 1;

    // --- block-wide rounds while the active list is large ---
    while (n > 32) {
        const unsigned epoch = (0x3FFFFu - round) << 13;   // strictly decreasing

        for (int i = tid; i < n; i += 1024) {
            const unsigned m = s_meta[cur[i]];
            const unsigned val = epoch | (m >> 19);
            const int off = (int)(m & 16383u);
            const int end = off + (int)((m >> 14) & 31u);
            for (int e = off; e < end; e++)
                atomicMin(&s_colmin[(unsigned)s_cand[e] & 8191u], val);
        }
        if (tid == 0) s_na[par] = 0;
        __syncthreads();

        for (int i = tid; i < n; i += 1024) {
            const int g = cur[i];
            const unsigned m = s_meta[g];
            const unsigned val = epoch | (m >> 19);
            const int off = (int)(m & 16383u);
            const int end = off + (int)((m >> 14) & 31u);
            unsigned long long best = ~0ULL;
            int bestE = -1;
            for (int e = off; e < end; e++) {
                const unsigned long long cd = s_cand[e];
                const unsigned j = (unsigned)cd & 8191u;
                if (!((s_claim[j >> 5] >> (j & 31u)) & 1u) && cd < best) {
                    best = cd;
                    bestE = e;
                }
            }
            if (best == ~0ULL) {
                s_res[g] = 0xFFFFu;                 // unmatched
            } else {
                const unsigned j = (unsigned)best & 8191u;
                if (s_colmin[j] == val) {
                    atomicOr(&s_claim[j >> 5], 1u << (j & 31u));
                    s_res[g] = (unsigned short)bestE;
                } else {
                    nxt[atomicAdd(&s_na[par], 1)] = (unsigned short)g;
                }
            }
        }
        __syncthreads();

        n = s_na[par];
        par ^= 1;
        round++;
        unsigned short* tmp = cur; cur = nxt; nxt = tmp;
    }

    // --- tail rounds: warp 0 only, no block barriers ---
    if (wid == 0) {
        while (n > 0) {
            const unsigned epoch = (0x3FFFFu - round) << 13;

            if (lane < n) {
                const unsigned m = s_meta[cur[lane]];
                const unsigned val = epoch | (m >> 19);
                const int off = (int)(m & 16383u);
                const int end = off + (int)((m >> 14) & 31u);
                for (int e = off; e < end; e++)
                    atomicMin(&s_colmin[(unsigned)s_cand[e] & 8191u], val);
            }
            __syncwarp();

            int survive = 0;
            int g = -1;
            if (lane < n) {
                g = cur[lane];
                const unsigned m = s_meta[g];
                const unsigned val = epoch | (m >> 19);
                const int off = (int)(m & 16383u);
                const int end = off + (int)((m >> 14) & 31u);
                unsigned long long best = ~0ULL;
                int bestE = -1;
                for (int e = off; e < end; e++) {
                    const unsigned long long cd = s_cand[e];
                    const unsigned j = (unsigned)cd & 8191u;
                    if (!((s_claim[j >> 5] >> (j & 31u)) & 1u) && cd < best) {
                        best = cd;
                        bestE = e;
                    }
                }
                if (best == ~0ULL) {
                    s_res[g] = 0xFFFFu;
                } else {
                    const unsigned j = (unsigned)best & 8191u;
                    if (s_colmin[j] == val) {
                        atomicOr(&s_claim[j >> 5], 1u << (j & 31u));
                        s_res[g] = (unsigned short)bestE;
                    } else {
                        survive = 1;
                    }
                }
            }
            __syncwarp();
            const unsigned sb = __ballot_sync(0xFFFFFFFFu, survive);
            if (survive) {
                const int pos = __popc(sb & ((1u << lane) - 1u));
                nxt[pos] = (unsigned short)g;
            }
            __syncwarp();
            n = __popc(sb);
            round++;
            unsigned short* tmp = cur; cur = nxt; nxt = tmp;
        }
    }
    __syncthreads();

    // --- fixed-order accumulation ---
    const float* truf  = (const float*)tru;
    const float* predf = (const float*)pred;
    float sd = 0.0f, sp = 0.0f;
    int nm = 0;
    for (int g = tid; g < ngrp; g += 1024) {
        const unsigned short r = s_res[g];
        if (r == 0xFFFFu) continue;
        const unsigned long long best = s_cand[r];
        const unsigned row = s_meta[g] >> 19;
        const unsigned j = (unsigned)best & 8191u;
        sd += __uint_as_float((unsigned)(best >> 13));
        nm++;
        const float dp = truf[4 * row + 3] - predf[4 * j + 3];
        sp = fmaf(dp, dp, sp);
    }
#pragma unroll
    for (int o = 16; o > 0; o >>= 1) {
        sd += __shfl_down_sync(0xFFFFFFFFu, sd, o);
        sp += __shfl_down_sync(0xFFFFFFFFu, sp, o);
        nm += __shfl_down_sync(0xFFFFFFFFu, nm, o);
    }
    if (lane == 0) { s_rd[wid] = sd; s_rp[wid] = sp; s_rn[wid] = nm; }

    // re-zero the cell counters for the next replay (graph-deterministic)
    for (int i = tid; i < NCELL; i += 1024) g_cellcnt[i] = 0;

    __syncthreads();
    if (tid == 0) {
        float tsd = 0.0f, tsp = 0.0f;
        int tnm = 0;
        for (int w = 0; w < 32; w++) { tsd += s_rd[w]; tsp += s_rp[w]; tnm += s_rn[w]; }
        const float fnm = (float)tnm;
        const float unm = (float)g_occ - fnm;
        const float mean_dist = tsd / fnm;
        const float prob_mse  = tsp / fnm;
        out[0] = (mean_dist + 10.0f * unm) + (prob_mse + unm);
    }
}

// ---------------------------------------------------------------------------
extern "C" void kernel_launch(void* const* d_in, const int* in_sizes, int n_in,
                              void* d_out, int out_size) {
    const float4* pred = (const float4*)d_in[0];
    const float4* tru  = (const float4*)d_in[1];
    float* out = (float*)d_out;

    bin_points<<<32, 256>>>(pred);

    // build_cand: PDL secondary of bin_points
    {
        cudaLaunchConfig_t cfg = {};
        cfg.gridDim = dim3(1024);
        cfg.blockDim = dim3(256);
        cudaLaunchAttribute attr[1];
        attr[0].id = cudaLaunchAttributeProgrammaticStreamSerialization;
        attr[0].val.programmaticStreamSerializationAllowed = 1;
        cfg.attrs = attr;
        cfg.numAttrs = 1;
        cudaLaunchKernelEx(&cfg, build_cand, tru);
    }

    // greedy_match: PDL secondary of build_cand
    {
        cudaFuncSetAttribute(greedy_match, cudaFuncAttributeMaxDynamicSharedMemorySize,
                             SMEM_BYTES);
        cudaLaunchConfig_t cfg = {};
        cfg.gridDim = dim3(1);
        cfg.blockDim = dim3(1024);
        cfg.dynamicSmemBytes = SMEM_BYTES;
        cudaLaunchAttribute attr[1];
        attr[0].id = cudaLaunchAttributeProgrammaticStreamSerialization;
        attr[0].val.programmaticStreamSerializationAllowed = 1;
        cfg.attrs = attr;
        cfg.numAttrs = 1;
        cudaLaunchKernelEx(&cfg, greedy_match, pred, tru, out);
    }
}

// round 14
// speedup vs baseline: 1.5022x; 1.0359x over previous
#include <cuda_runtime.h>

#define NT 8192          // true rows
#define NP 8192          // pred cols
#define CAPR 31          // max candidates kept per row (fits 5-bit cnt field)
#define MAXC 12288       // max total compacted candidates (expected ~8.8K)
#define NCELL 8000       // 20x20x20 unit cells
#define CELLCAP 16       // slots per cell (lambda ~0.51 occupied/cell)

// Scratch (device globals — allocation-free; zero-initialized at module load,
// and greedy_match re-zeroes g_cellcnt at the end of every run).
__device__ int g_cellcnt[NCELL];
__device__ float4 g_pts[NCELL * CELLCAP];       // xyz + pred index as int bits
__device__ unsigned long long g_pack;           // hi32 = ngroups, lo32 = ncand total
__device__ unsigned g_meta[NT];                 // row<<19 | cnt<<14 | offset
__device__ unsigned long long g_ccand[MAXC];    // key = (f32bits(d) << 13) | j
__device__ unsigned short g_crow[MAXC];         // owning row per candidate slot
__device__ int g_occ;                           // count of occupied true points

__device__ __forceinline__ void pdl_wait() {
    asm volatile("griddepcontrol.wait;" ::: "memory");
}

__device__ __forceinline__ int cell_of(float x, float y, float z) {
    const int cx = min(19, (int)x);
    const int cy = min(19, (int)y);
    const int cz = min(19, (int)z);
    return (cx * 20 + cy) * 20 + cz;
}

// ---------------------------------------------------------------------------
// Phase 1a: bin occupied preds into fixed-capacity cells; reset run counters.
// ---------------------------------------------------------------------------
__global__ __launch_bounds__(256) void bin_points(const float4* __restrict__ pred) {
    const int i = blockIdx.x * 256 + threadIdx.x;
    if (i == 0) { g_pack = 0ULL; g_occ = 0; }
    const float4 p = pred[i];
    if (p.w >= 0.5f) {
        const int c = cell_of(p.x, p.y, p.z);
        const int idx = atomicAdd(&g_cellcnt[c], 1);
        if (idx < CELLCAP)
            g_pts[c * CELLCAP + idx] = make_float4(p.x, p.y, p.z, __int_as_float(i));
    }
}

// ---------------------------------------------------------------------------
// Phase 1b: candidate generation, WARP per true row; lane L<27 owns one of the
// 3x3x3 neighbor cells. PDL secondary: tru[] load + cell math pre-wait.
// Emits g_ccand (key) AND g_crow (owning row) per compacted slot.
// ---------------------------------------------------------------------------
#define WPB 8   // warps per block
__global__ __launch_bounds__(256) void build_cand(const float4* __restrict__ tru) {
    __shared__ unsigned long long stage[WPB][32];
    __shared__ int s_cnt[WPB];
    __shared__ int s_occ;
    const int wip  = threadIdx.x >> 5;
    const int lane = threadIdx.x & 31;
    const int row  = blockIdx.x * WPB + wip;

    if (threadIdx.x == 0) s_occ = 0;
    if (lane == 0) s_cnt[wip] = 0;

    // input-independent prologue: load true point, compute neighbor cell
    const float4 t = tru[row];
    const bool occ = (t.w >= 0.5f);
    int c = -1;
    if (occ && lane < 27) {
        const int cx = min(19, (int)t.x);
        const int cy = min(19, (int)t.y);
        const int cz = min(19, (int)t.z);
        const int X = cx + lane / 9 - 1;
        const int Y = cy + (lane / 3) % 3 - 1;
        const int Z = cz + lane % 3 - 1;
        if (X >= 0 && X < 20 && Y >= 0 && Y < 20 && Z >= 0 && Z < 20)
            c = (X * 20 + Y) * 20 + Z;
    }
    __syncthreads();

    pdl_wait();   // bin_points output (g_cellcnt, g_pts, g_pack=0) now visible

    if (c >= 0) {
        const int cnt = min(g_cellcnt[c], CELLCAP);
        for (int e = 0; e < cnt; e++) {
            const float4 p = g_pts[c * CELLCAP + e];
            const float dx = t.x - p.x, dy = t.y - p.y, dz = t.z - p.z;
            float d2 = dx * dx;
            d2 = fmaf(dy, dy, d2);
            d2 = fmaf(dz, dz, d2);
            if (d2 <= 1.0000002f) {
                const float d = __fsqrt_rn(d2);
                if (d <= 1.0f) {
                    const int idx = atomicAdd(&s_cnt[wip], 1);
                    if (idx < CAPR)
                        stage[wip][idx] =
                            (((unsigned long long)__float_as_uint(d)) << 13) |
                            (unsigned)__float_as_int(p.w);
                }
            }
        }
    }
    __syncwarp();

    const int cnt = min(s_cnt[wip], CAPR);
    int base = 0;
    if (lane == 0 && cnt > 0) {
        const unsigned long long old =
            atomicAdd(&g_pack, (1ULL << 32) | (unsigned long long)(unsigned)cnt);
        const unsigned gidx = (unsigned)(old >> 32);
        base = (int)(old & 0xFFFFFFFFu);
        const int wcnt = (base + cnt <= MAXC) ? cnt : 0;   // overflow guard (p~0)
        g_meta[gidx] = ((unsigned)row << 19) | ((unsigned)wcnt << 14) |
                       (unsigned)(base & 16383);
    }
    base = __shfl_sync(0xFFFFFFFFu, base, 0);
    if (lane < cnt && base + lane < MAXC) {
        g_ccand[base + lane] = stage[wip][lane];
        g_crow[base + lane]  = (unsigned short)row;
    }

    // ONE count per occupied row (warp-per-row: lane 0 only!)
    if (lane == 0 && occ) atomicAdd(&s_occ, 1);
    __syncthreads();
    if (threadIdx.x == 0 && s_occ) atomicAdd(&g_occ, s_occ);
}

// ---------------------------------------------------------------------------
// Phase 2: PDL secondary. Round-based greedy, epoch-tagged colmin.
// Round-0 pass A is FUSED with the global->smem candidate copy: each slot is
// read from L2 once, stored to s_cand, and registered in colmin using
// g_crow[i] — deleting one 12K-element smem pass and one block barrier.
// Identity active list in round 0; ping-pong u16 lists after; warp-0 tail.
//
// Dynamic smem layout (bytes): unchanged from round 8.
// ---------------------------------------------------------------------------
#define SMEM_BYTES 214432

__global__ __launch_bounds__(1024, 1) void greedy_match(const float4* __restrict__ pred,
                                                        const float4* __restrict__ tru,
                                                        float* __restrict__ out) {
    extern __shared__ unsigned char sm[];
    unsigned long long* s_cand   = (unsigned long long*)sm;
    unsigned*           s_meta   = (unsigned*)(sm + 98304);
    unsigned*           s_colmin = (unsigned*)(sm + 131072);
    unsigned*           s_claim  = (unsigned*)(sm + 163840);
    int*                s_na     = (int*)(sm + 164864);
    float*              s_rd     = (float*)(sm + 164872);
    float*              s_rp     = (float*)(sm + 165000);
    int*                s_rn     = (int*)(sm + 165128);
    unsigned short*     s_listA  = (unsigned short*)(sm + 165256);
    unsigned short*     s_listB  = (unsigned short*)(sm + 181640);
    unsigned short*     s_res    = (unsigned short*)(sm + 198024);

    const int tid  = threadIdx.x;
    const int lane = tid & 31;
    const int wid  = tid >> 5;

    // --- input-independent prologue (overlaps with build_cand via PDL) ---
    if (tid < 256) s_claim[tid] = 0u;
    for (int i = tid; i < NP; i += 1024) s_colmin[i] = 0xFFFFFFFFu;

    pdl_wait();   // build_cand output (g_pack, g_meta, g_ccand, g_crow) visible

    const unsigned long long pack = g_pack;
    const int ngrp = (int)(pack >> 32);
    const int ctot = min((int)(pack & 0xFFFFFFFFu), MAXC);

    // --- FUSED: copy candidates to smem + round-0 colmin registration ---
    {
        const unsigned epoch0 = 0x3FFFFu << 13;
        for (int i = tid; i < ctot; i += 1024) {
            const unsigned long long cd = g_ccand[i];
            const unsigned rw = g_crow[i];
            s_cand[i] = cd;
            atomicMin(&s_colmin[(unsigned)cd & 8191u], epoch0 | rw);
        }
    }
    for (int g = tid; g < ngrp; g += 1024) s_meta[g] = g_meta[g];
    if (tid == 0) s_na[0] = 0;
    __syncthreads();

    // ---------------- round 0 pass B: identity active list ----------------
    {
        const unsigned epoch = 0x3FFFFu << 13;
        for (int g = tid; g < ngrp; g += 1024) {
            const unsigned m = s_meta[g];
            const unsigned val = epoch | (m >> 19);
            const int off = (int)(m & 16383u);
            const int end = off + (int)((m >> 14) & 31u);
            unsigned long long best = ~0ULL;
            int bestE = -1;
            for (int e = off; e < end; e++) {
                const unsigned long long cd = s_cand[e];
                const unsigned j = (unsigned)cd & 8191u;
                if (!((s_claim[j >> 5] >> (j & 31u)) & 1u) && cd < best) {
                    best = cd;
                    bestE = e;
                }
            }
            if (best == ~0ULL) {
                s_res[g] = 0xFFFFu;                 // unmatched
            } else {
                const unsigned j = (unsigned)best & 8191u;
                if (s_colmin[j] == val) {
                    atomicOr(&s_claim[j >> 5], 1u << (j & 31u));
                    s_res[g] = (unsigned short)bestE;
                } else {
                    s_listA[atomicAdd(&s_na[0], 1)] = (unsigned short)g;
                }
            }
        }
        __syncthreads();
    }

    unsigned short* cur = s_listA;
    unsigned short* nxt = s_listB;
    int n = s_na[0];
    int par = 1;
    unsigned round = 1;

    // --- block-wide rounds while the active list is large ---
    while (n > 32) {
        const unsigned epoch = (0x3FFFFu - round) << 13;   // strictly decreasing

        for (int i = tid; i < n; i += 1024) {
            const unsigned m = s_meta[cur[i]];
            const unsigned val = epoch | (m >> 19);
            const int off = (int)(m & 16383u);
            const int end = off + (int)((m >> 14) & 31u);
            for (int e = off; e < end; e++)
                atomicMin(&s_colmin[(unsigned)s_cand[e] & 8191u], val);
        }
        if (tid == 0) s_na[par] = 0;
        __syncthreads();

        for (int i = tid; i < n; i += 1024) {
            const int g = cur[i];
            const unsigned m = s_meta[g];
            const unsigned val = epoch | (m >> 19);
            const int off = (int)(m & 16383u);
            const int end = off + (int)((m >> 14) & 31u);
            unsigned long long best = ~0ULL;
            int bestE = -1;
            for (int e = off; e < end; e++) {
                const unsigned long long cd = s_cand[e];
                const unsigned j = (unsigned)cd & 8191u;
                if (!((s_claim[j >> 5] >> (j & 31u)) & 1u) && cd < best) {
                    best = cd;
                    bestE = e;
                }
            }
            if (best == ~0ULL) {
                s_res[g] = 0xFFFFu;                 // unmatched
            } else {
                const unsigned j = (unsigned)best & 8191u;
                if (s_colmin[j] == val) {
                    atomicOr(&s_claim[j >> 5], 1u << (j & 31u));
                    s_res[g] = (unsigned short)bestE;
                } else {
                    nxt[atomicAdd(&s_na[par], 1)] = (unsigned short)g;
                }
            }
        }
        __syncthreads();

        n = s_na[par];
        par ^= 1;
        round++;
        unsigned short* tmp = cur; cur = nxt; nxt = tmp;
    }

    // --- tail rounds: warp 0 only, no block barriers ---
    if (wid == 0) {
        while (n > 0) {
            const unsigned epoch = (0x3FFFFu - round) << 13;

            if (lane < n) {
                const unsigned m = s_meta[cur[lane]];
                const unsigned val = epoch | (m >> 19);
                const int off = (int)(m & 16383u);
                const int end = off + (int)((m >> 14) & 31u);
                for (int e = off; e < end; e++)
                    atomicMin(&s_colmin[(unsigned)s_cand[e] & 8191u], val);
            }
            __syncwarp();

            int survive = 0;
            int g = -1;
            if (lane < n) {
                g = cur[lane];
                const unsigned m = s_meta[g];
                const unsigned val = epoch | (m >> 19);
                const int off = (int)(m & 16383u);
                const int end = off + (int)((m >> 14) & 31u);
                unsigned long long best = ~0ULL;
                int bestE = -1;
                for (int e = off; e < end; e++) {
                    const unsigned long long cd = s_cand[e];
                    const unsigned j = (unsigned)cd & 8191u;
                    if (!((s_claim[j >> 5] >> (j & 31u)) & 1u) && cd < best) {
                        best = cd;
                        bestE = e;
                    }
                }
                if (best == ~0ULL) {
                    s_res[g] = 0xFFFFu;
                } else {
                    const unsigned j = (unsigned)best & 8191u;
                    if (s_colmin[j] == val) {
                        atomicOr(&s_claim[j >> 5], 1u << (j & 31u));
                        s_res[g] = (unsigned short)bestE;
                    } else {
                        survive = 1;
                    }
                }
            }
            __syncwarp();
            const unsigned sb = __ballot_sync(0xFFFFFFFFu, survive);
            if (survive) {
                const int pos = __popc(sb & ((1u << lane) - 1u));
                nxt[pos] = (unsigned short)g;
            }
            __syncwarp();
            n = __popc(sb);
            round++;
            unsigned short* tmp = cur; cur = nxt; nxt = tmp;
        }
    }
    __syncthreads();

    // --- fixed-order accumulation ---
    const float* truf  = (const float*)tru;
    const float* predf = (const float*)pred;
    float sd = 0.0f, sp = 0.0f;
    int nm = 0;
    for (int g = tid; g < ngrp; g += 1024) {
        const unsigned short r = s_res[g];
        if (r == 0xFFFFu) continue;
        const unsigned long long best = s_cand[r];
        const unsigned row = s_meta[g] >> 19;
        const unsigned j = (unsigned)best & 8191u;
        sd += __uint_as_float((unsigned)(best >> 13));
        nm++;
        const float dp = truf[4 * row + 3] - predf[4 * j + 3];
        sp = fmaf(dp, dp, sp);
    }
#pragma unroll
    for (int o = 16; o > 0; o >>= 1) {
        sd += __shfl_down_sync(0xFFFFFFFFu, sd, o);
        sp += __shfl_down_sync(0xFFFFFFFFu, sp, o);
        nm += __shfl_down_sync(0xFFFFFFFFu, nm, o);
    }
    if (lane == 0) { s_rd[wid] = sd; s_rp[wid] = sp; s_rn[wid] = nm; }

    // re-zero the cell counters for the next replay (graph-deterministic)
    for (int i = tid; i < NCELL; i += 1024) g_cellcnt[i] = 0;

    __syncthreads();
    if (tid == 0) {
        float tsd = 0.0f, tsp = 0.0f;
        int tnm = 0;
        for (int w = 0; w < 32; w++) { tsd += s_rd[w]; tsp += s_rp[w]; tnm += s_rn[w]; }
        const float fnm = (float)tnm;
        const float unm = (float)g_occ - fnm;
        const float mean_dist = tsd / fnm;
        const float prob_mse  = tsp / fnm;
        out[0] = (mean_dist + 10.0f * unm) + (prob_mse + unm);
    }
}

// ---------------------------------------------------------------------------
extern "C" void kernel_launch(void* const* d_in, const int* in_sizes, int n_in,
                              void* d_out, int out_size) {
    const float4* pred = (const float4*)d_in[0];
    const float4* tru  = (const float4*)d_in[1];
    float* out = (float*)d_out;

    bin_points<<<32, 256>>>(pred);

    // build_cand: PDL secondary of bin_points
    {
        cudaLaunchConfig_t cfg = {};
        cfg.gridDim = dim3(1024);
        cfg.blockDim = dim3(256);
        cudaLaunchAttribute attr[1];
        attr[0].id = cudaLaunchAttributeProgrammaticStreamSerialization;
        attr[0].val.programmaticStreamSerializationAllowed = 1;
        cfg.attrs = attr;
        cfg.numAttrs = 1;
        cudaLaunchKernelEx(&cfg, build_cand, tru);
    }

    // greedy_match: PDL secondary of build_cand
    {
        cudaFuncSetAttribute(greedy_match, cudaFuncAttributeMaxDynamicSharedMemorySize,
                             SMEM_BYTES);
        cudaLaunchConfig_t cfg = {};
        cfg.gridDim = dim3(1);
        cfg.blockDim = dim3(1024);
        cfg.dynamicSmemBytes = SMEM_BYTES;
        cudaLaunchAttribute attr[1];
        attr[0].id = cudaLaunchAttributeProgrammaticStreamSerialization;
        attr[0].val.programmaticStreamSerializationAllowed = 1;
        cfg.attrs = attr;
        cfg.numAttrs = 1;
        cudaLaunchKernelEx(&cfg, greedy_match, pred, tru, out);
    }
}

// round 15
// speedup vs baseline: 1.5090x; 1.0045x over previous
#include <cuda_runtime.h>

#define NT 8192          // true rows
#define NP 8192          // pred cols
#define CAPR 31          // max candidates kept per row (fits 5-bit cnt field)
#define MAXC 12288       // max total compacted candidates (expected ~8.8K)
#define NCELL 8000       // 20x20x20 unit cells
#define CELLCAP 16       // slots per cell (lambda ~0.51 occupied/cell)

// Scratch (device globals — allocation-free; zero-initialized at module load,
// and greedy_match re-zeroes g_cellcnt at the end of every run).
__device__ int g_cellcnt[NCELL];
__device__ float4 g_pts[NCELL * CELLCAP];       // xyz + pred index as int bits
__device__ unsigned long long g_pack;           // hi32 = ngroups, lo32 = ncand total
__device__ unsigned g_meta[NT];                 // row<<19 | cnt<<14 | offset
__device__ unsigned long long g_ccand[MAXC];    // key = (f32bits(d) << 13) | j
__device__ unsigned short g_crow[MAXC];         // owning row per candidate slot
__device__ int g_occ;                           // count of occupied true points

__device__ __forceinline__ void pdl_wait() {
    asm volatile("griddepcontrol.wait;" ::: "memory");
}
__device__ __forceinline__ void pdl_trigger() {
    asm volatile("griddepcontrol.launch_dependents;" ::: "memory");
}

__device__ __forceinline__ int cell_of(float x, float y, float z) {
    const int cx = min(19, (int)x);
    const int cy = min(19, (int)y);
    const int cz = min(19, (int)z);
    return (cx * 20 + cy) * 20 + cz;
}

// ---------------------------------------------------------------------------
// Phase 1a: bin occupied preds into fixed-capacity cells; reset run counters.
// Early pdl_trigger: dependent build_cand starts its launch ramp immediately;
// its pdl_wait still blocks until this kernel's memory is visible.
// ---------------------------------------------------------------------------
__global__ __launch_bounds__(256) void bin_points(const float4* __restrict__ pred) {
    pdl_trigger();
    const int i = blockIdx.x * 256 + threadIdx.x;
    if (i == 0) { g_pack = 0ULL; g_occ = 0; }
    const float4 p = pred[i];
    if (p.w >= 0.5f) {
        const int c = cell_of(p.x, p.y, p.z);
        const int idx = atomicAdd(&g_cellcnt[c], 1);
        if (idx < CELLCAP)
            g_pts[c * CELLCAP + idx] = make_float4(p.x, p.y, p.z, __int_as_float(i));
    }
}

// ---------------------------------------------------------------------------
// Phase 1b: candidate generation, WARP per true row; lane L<27 owns one of the
// 3x3x3 neighbor cells. PDL secondary: tru[] load + cell math pre-wait.
// Early pdl_trigger so greedy_match (209KB smem carve-out) ramps in parallel.
// Emits g_ccand (key) AND g_crow (owning row) per compacted slot.
// ---------------------------------------------------------------------------
#define WPB 8   // warps per block
__global__ __launch_bounds__(256) void build_cand(const float4* __restrict__ tru) {
    pdl_trigger();
    __shared__ unsigned long long stage[WPB][32];
    __shared__ int s_cnt[WPB];
    __shared__ int s_occ;
    const int wip  = threadIdx.x >> 5;
    const int lane = threadIdx.x & 31;
    const int row  = blockIdx.x * WPB + wip;

    if (threadIdx.x == 0) s_occ = 0;
    if (lane == 0) s_cnt[wip] = 0;

    // input-independent prologue: load true point, compute neighbor cell
    const float4 t = tru[row];
    const bool occ = (t.w >= 0.5f);
    int c = -1;
    if (occ && lane < 27) {
        const int cx = min(19, (int)t.x);
        const int cy = min(19, (int)t.y);
        const int cz = min(19, (int)t.z);
        const int X = cx + lane / 9 - 1;
        const int Y = cy + (lane / 3) % 3 - 1;
        const int Z = cz + lane % 3 - 1;
        if (X >= 0 && X < 20 && Y >= 0 && Y < 20 && Z >= 0 && Z < 20)
            c = (X * 20 + Y) * 20 + Z;
    }
    __syncthreads();

    pdl_wait();   // bin_points output (g_cellcnt, g_pts, g_pack=0) now visible

    if (c >= 0) {
        const int cnt = min(g_cellcnt[c], CELLCAP);
        for (int e = 0; e < cnt; e++) {
            const float4 p = g_pts[c * CELLCAP + e];
            const float dx = t.x - p.x, dy = t.y - p.y, dz = t.z - p.z;
            float d2 = dx * dx;
            d2 = fmaf(dy, dy, d2);
            d2 = fmaf(dz, dz, d2);
            if (d2 <= 1.0000002f) {
                const float d = __fsqrt_rn(d2);
                if (d <= 1.0f) {
                    const int idx = atomicAdd(&s_cnt[wip], 1);
                    if (idx < CAPR)
                        stage[wip][idx] =
                            (((unsigned long long)__float_as_uint(d)) << 13) |
                            (unsigned)__float_as_int(p.w);
                }
            }
        }
    }
    __syncwarp();

    const int cnt = min(s_cnt[wip], CAPR);
    int base = 0;
    if (lane == 0 && cnt > 0) {
        const unsigned long long old =
            atomicAdd(&g_pack, (1ULL << 32) | (unsigned long long)(unsigned)cnt);
        const unsigned gidx = (unsigned)(old >> 32);
        base = (int)(old & 0xFFFFFFFFu);
        const int wcnt = (base + cnt <= MAXC) ? cnt : 0;   // overflow guard (p~0)
        g_meta[gidx] = ((unsigned)row << 19) | ((unsigned)wcnt << 14) |
                       (unsigned)(base & 16383);
    }
    base = __shfl_sync(0xFFFFFFFFu, base, 0);
    if (lane < cnt && base + lane < MAXC) {
        g_ccand[base + lane] = stage[wip][lane];
        g_crow[base + lane]  = (unsigned short)row;
    }

    // ONE count per occupied row (warp-per-row: lane 0 only!)
    if (lane == 0 && occ) atomicAdd(&s_occ, 1);
    __syncthreads();
    if (threadIdx.x == 0 && s_occ) atomicAdd(&g_occ, s_occ);
}

// ---------------------------------------------------------------------------
// Phase 2: PDL secondary. Round-based greedy, epoch-tagged colmin.
// Round-0 pass A FUSED with the global->smem candidate copy (one L2 read per
// slot feeds both s_cand store and colmin registration via g_crow).
// Identity active list in round 0; ping-pong u16 lists after; warp-0 tail.
//
// Dynamic smem layout (bytes): unchanged from round 8.
// ---------------------------------------------------------------------------
#define SMEM_BYTES 214432

__global__ __launch_bounds__(1024, 1) void greedy_match(const float4* __restrict__ pred,
                                                        const float4* __restrict__ tru,
                                                        float* __restrict__ out) {
    extern __shared__ unsigned char sm[];
    unsigned long long* s_cand   = (unsigned long long*)sm;
    unsigned*           s_meta   = (unsigned*)(sm + 98304);
    unsigned*           s_colmin = (unsigned*)(sm + 131072);
    unsigned*           s_claim  = (unsigned*)(sm + 163840);
    int*                s_na     = (int*)(sm + 164864);
    float*              s_rd     = (float*)(sm + 164872);
    float*              s_rp     = (float*)(sm + 165000);
    int*                s_rn     = (int*)(sm + 165128);
    unsigned short*     s_listA  = (unsigned short*)(sm + 165256);
    unsigned short*     s_listB  = (unsigned short*)(sm + 181640);
    unsigned short*     s_res    = (unsigned short*)(sm + 198024);

    const int tid  = threadIdx.x;
    const int lane = tid & 31;
    const int wid  = tid >> 5;

    // --- input-independent prologue (overlaps with build_cand via PDL) ---
    if (tid < 256) s_claim[tid] = 0u;
    for (int i = tid; i < NP; i += 1024) s_colmin[i] = 0xFFFFFFFFu;

    pdl_wait();   // build_cand output (g_pack, g_meta, g_ccand, g_crow) visible

    const unsigned long long pack = g_pack;
    const int ngrp = (int)(pack >> 32);
    const int ctot = min((int)(pack & 0xFFFFFFFFu), MAXC);

    // --- FUSED: copy candidates to smem + round-0 colmin registration ---
    {
        const unsigned epoch0 = 0x3FFFFu << 13;
        for (int i = tid; i < ctot; i += 1024) {
            const unsigned long long cd = g_ccand[i];
            const unsigned rw = g_crow[i];
            s_cand[i] = cd;
            atomicMin(&s_colmin[(unsigned)cd & 8191u], epoch0 | rw);
        }
    }
    for (int g = tid; g < ngrp; g += 1024) s_meta[g] = g_meta[g];
    if (tid == 0) s_na[0] = 0;
    __syncthreads();

    // ---------------- round 0 pass B: identity active list ----------------
    {
        const unsigned epoch = 0x3FFFFu << 13;
        for (int g = tid; g < ngrp; g += 1024) {
            const unsigned m = s_meta[g];
            const unsigned val = epoch | (m >> 19);
            const int off = (int)(m & 16383u);
            const int end = off + (int)((m >> 14) & 31u);
            unsigned long long best = ~0ULL;
            int bestE = -1;
            for (int e = off; e < end; e++) {
                const unsigned long long cd = s_cand[e];
                const unsigned j = (unsigned)cd & 8191u;
                if (!((s_claim[j >> 5] >> (j & 31u)) & 1u) && cd < best) {
                    best = cd;
                    bestE = e;
                }
            }
            if (best == ~0ULL) {
                s_res[g] = 0xFFFFu;                 // unmatched
            } else {
                const unsigned j = (unsigned)best & 8191u;
                if (s_colmin[j] == val) {
                    atomicOr(&s_claim[j >> 5], 1u << (j & 31u));
                    s_res[g] = (unsigned short)bestE;
                } else {
                    s_listA[atomicAdd(&s_na[0], 1)] = (unsigned short)g;
                }
            }
        }
        __syncthreads();
    }

    unsigned short* cur = s_listA;
    unsigned short* nxt = s_listB;
    int n = s_na[0];
    int par = 1;
    unsigned round = 1;

    // --- block-wide rounds while the active list is large ---
    while (n > 32) {
        const unsigned epoch = (0x3FFFFu - round) << 13;   // strictly decreasing

        for (int i = tid; i < n; i += 1024) {
            const unsigned m = s_meta[cur[i]];
            const unsigned val = epoch | (m >> 19);
            const int off = (int)(m & 16383u);
            const int end = off + (int)((m >> 14) & 31u);
            for (int e = off; e < end; e++)
                atomicMin(&s_colmin[(unsigned)s_cand[e] & 8191u], val);
        }
        if (tid == 0) s_na[par] = 0;
        __syncthreads();

        for (int i = tid; i < n; i += 1024) {
            const int g = cur[i];
            const unsigned m = s_meta[g];
            const unsigned val = epoch | (m >> 19);
            const int off = (int)(m & 16383u);
            const int end = off + (int)((m >> 14) & 31u);
            unsigned long long best = ~0ULL;
            int bestE = -1;
            for (int e = off; e < end; e++) {
                const unsigned long long cd = s_cand[e];
                const unsigned j = (unsigned)cd & 8191u;
                if (!((s_claim[j >> 5] >> (j & 31u)) & 1u) && cd < best) {
                    best = cd;
                    bestE = e;
                }
            }
            if (best == ~0ULL) {
                s_res[g] = 0xFFFFu;                 // unmatched
            } else {
                const unsigned j = (unsigned)best & 8191u;
                if (s_colmin[j] == val) {
                    atomicOr(&s_claim[j >> 5], 1u << (j & 31u));
                    s_res[g] = (unsigned short)bestE;
                } else {
                    nxt[atomicAdd(&s_na[par], 1)] = (unsigned short)g;
                }
            }
        }
        __syncthreads();

        n = s_na[par];
        par ^= 1;
        round++;
        unsigned short* tmp = cur; cur = nxt; nxt = tmp;
    }

    // --- tail rounds: warp 0 only, no block barriers ---
    if (wid == 0) {
        while (n > 0) {
            const unsigned epoch = (0x3FFFFu - round) << 13;

            if (lane < n) {
                const unsigned m = s_meta[cur[lane]];
                const unsigned val = epoch | (m >> 19);
                const int off = (int)(m & 16383u);
                const int end = off + (int)((m >> 14) & 31u);
                for (int e = off; e < end; e++)
                    atomicMin(&s_colmin[(unsigned)s_cand[e] & 8191u], val);
            }
            __syncwarp();

            int survive = 0;
            int g = -1;
            if (lane < n) {
                g = cur[lane];
                const unsigned m = s_meta[g];
                const unsigned val = epoch | (m >> 19);
                const int off = (int)(m & 16383u);
                const int end = off + (int)((m >> 14) & 31u);
                unsigned long long best = ~0ULL;
                int bestE = -1;
                for (int e = off; e < end; e++) {
                    const unsigned long long cd = s_cand[e];
                    const unsigned j = (unsigned)cd & 8191u;
                    if (!((s_claim[j >> 5] >> (j & 31u)) & 1u) && cd < best) {
                        best = cd;
                        bestE = e;
                    }
                }
                if (best == ~0ULL) {
                    s_res[g] = 0xFFFFu;
                } else {
                    const unsigned j = (unsigned)best & 8191u;
                    if (s_colmin[j] == val) {
                        atomicOr(&s_claim[j >> 5], 1u << (j & 31u));
                        s_res[g] = (unsigned short)bestE;
                    } else {
                        survive = 1;
                    }
                }
            }
            __syncwarp();
            const unsigned sb = __ballot_sync(0xFFFFFFFFu, survive);
            if (survive) {
                const int pos = __popc(sb & ((1u << lane) - 1u));
                nxt[pos] = (unsigned short)g;
            }
            __syncwarp();
            n = __popc(sb);
            round++;
            unsigned short* tmp = cur; cur = nxt; nxt = tmp;
        }
    }
    __syncthreads();

    // --- fixed-order accumulation ---
    const float* truf  = (const float*)tru;
    const float* predf = (const float*)pred;
    float sd = 0.0f, sp = 0.0f;
    int nm = 0;
    for (int g = tid; g < ngrp; g += 1024) {
        const unsigned short r = s_res[g];
        if (r == 0xFFFFu) continue;
        const unsigned long long best = s_cand[r];
        const unsigned row = s_meta[g] >> 19;
        const unsigned j = (unsigned)best & 8191u;
        sd += __uint_as_float((unsigned)(best >> 13));
        nm++;
        const float dp = truf[4 * row + 3] - predf[4 * j + 3];
        sp = fmaf(dp, dp, sp);
    }
#pragma unroll
    for (int o = 16; o > 0; o >>= 1) {
        sd += __shfl_down_sync(0xFFFFFFFFu, sd, o);
        sp += __shfl_down_sync(0xFFFFFFFFu, sp, o);
        nm += __shfl_down_sync(0xFFFFFFFFu, nm, o);
    }
    if (lane == 0) { s_rd[wid] = sd; s_rp[wid] = sp; s_rn[wid] = nm; }

    // re-zero the cell counters for the next replay (graph-deterministic)
    for (int i = tid; i < NCELL; i += 1024) g_cellcnt[i] = 0;

    __syncthreads();
    if (tid == 0) {
        float tsd = 0.0f, tsp = 0.0f;
        int tnm = 0;
        for (int w = 0; w < 32; w++) { tsd += s_rd[w]; tsp += s_rp[w]; tnm += s_rn[w]; }
        const float fnm = (float)tnm;
        const float unm = (float)g_occ - fnm;
        const float mean_dist = tsd / fnm;
        const float prob_mse  = tsp / fnm;
        out[0] = (mean_dist + 10.0f * unm) + (prob_mse + unm);
    }
}

// ---------------------------------------------------------------------------
extern "C" void kernel_launch(void* const* d_in, const int* in_sizes, int n_in,
                              void* d_out, int out_size) {
    const float4* pred = (const float4*)d_in[0];
    const float4* tru  = (const float4*)d_in[1];
    float* out = (float*)d_out;

    bin_points<<<32, 256>>>(pred);

    // build_cand: PDL secondary of bin_points
    {
        cudaLaunchConfig_t cfg = {};
        cfg.gridDim = dim3(1024);
        cfg.blockDim = dim3(256);
        cudaLaunchAttribute attr[1];
        attr[0].id = cudaLaunchAttributeProgrammaticStreamSerialization;
        attr[0].val.programmaticStreamSerializationAllowed = 1;
        cfg.attrs = attr;
        cfg.numAttrs = 1;
        cudaLaunchKernelEx(&cfg, build_cand, tru);
    }

    // greedy_match: PDL secondary of build_cand
    {
        cudaFuncSetAttribute(greedy_match, cudaFuncAttributeMaxDynamicSharedMemorySize,
                             SMEM_BYTES);
        cudaLaunchConfig_t cfg = {};
        cfg.gridDim = dim3(1);
        cfg.blockDim = dim3(1024);
        cfg.dynamicSmemBytes = SMEM_BYTES;
        cudaLaunchAttribute attr[1];
        attr[0].id = cudaLaunchAttributeProgrammaticStreamSerialization;
        attr[0].val.programmaticStreamSerializationAllowed = 1;
        cfg.attrs = attr;
        cfg.numAttrs = 1;
        cudaLaunchKernelEx(&cfg, greedy_match, pred, tru, out);
    }
}